// round 13
// baseline (speedup 1.0000x reference)
#include <cuda_runtime.h>

#define NSIDE    48
#define NPIX     2304          // 48*48
#define LDW      52            // padded smem row stride (floats)
#define NTHREADS 576           // 18 warps: 6x3 grid of 8x16 warp tiles
#define NWARPS   18
#define INV_EPS  100.0f
#define MAXB     64

__device__ float g_cost[MAXB];
__device__ unsigned int g_count = 0;

typedef unsigned long long u64t;

__device__ __forceinline__ float4 ld4(const float* p) {
    return *reinterpret_cast<const float4*>(p);
}
__device__ __forceinline__ void st4(float* p, float4 v) {
    *reinterpret_cast<float4*>(p) = v;
}
__device__ __forceinline__ float mass_of(float x) {
    return fminf(fmaxf(x, 0.0f), 1e9f) + 1e-9f;
}

// ---- packed f32x2 helpers --------------------------------------------------
__device__ __forceinline__ u64t pack2(float v) {
    u64t r; asm("mov.b64 %0, {%1, %1};" : "=l"(r) : "f"(v)); return r;
}
__device__ __forceinline__ u64t ffma2(u64t a, u64t b, u64t c) {
    u64t d; asm("fma.rn.f32x2 %0, %1, %2, %3;" : "=l"(d) : "l"(a), "l"(b), "l"(c));
    return d;
}
__device__ __forceinline__ float2 unpack2(u64t v) {
    float2 f; asm("mov.b64 {%0, %1}, %2;" : "=f"(f.x), "=f"(f.y) : "l"(v));
    return f;
}

// ---------------------------------------------------------------------------
// block reduce (all threads receive the sum; deterministic order)
// ---------------------------------------------------------------------------
__device__ __forceinline__ float block_reduce(float val, float* red) {
#pragma unroll
    for (int o = 16; o; o >>= 1) val += __shfl_down_sync(0xffffffffu, val, o);
    if ((threadIdx.x & 31) == 0) red[threadIdx.x >> 5] = val;
    __syncthreads();
    float s = red[0];
#pragma unroll
    for (int w = 1; w < NWARPS; w++) s += red[w];
    __syncthreads();
    return s;
}

// ---------------------------------------------------------------------------
// Dense 48x48 matmul slice, 8x16 warp tiles, 1 row x 4 cols per thread:
//   acc[j] (f32x2) = (A*B)[rA, c0 + 2j .. c0+2j+1]
// A: one LDS.128 per 4 k-iters; 8 distinct rows/warp at banks 20*lr mod 32
// (all distinct, segments tile all 32 banks) -> 1 wavefront.
// B: 4 distinct 16B segments, 8-lane broadcast each -> 1 wavefront/iter.
// ---------------------------------------------------------------------------
__device__ __forceinline__ void mm_wb(const float* __restrict__ A,
                                      const float* __restrict__ B,
                                      int rA, int c0, u64t acc[2]) {
    acc[0] = acc[1] = 0ull;
    const float* a0p = A + rA * LDW;
#pragma unroll 4
    for (int b4 = 0; b4 < NSIDE; b4 += 4) {
        float4 av = ld4(a0p + b4);
        const float* bp = B + b4 * LDW + c0;
#pragma unroll
        for (int k = 0; k < 4; k++) {
            float as = (k == 0) ? av.x : (k == 1) ? av.y : (k == 2) ? av.z : av.w;
            u64t a = pack2(as);
            ulonglong2 bv = *reinterpret_cast<const ulonglong2*>(bp + k * LDW);
            acc[0] = ffma2(a, bv.x, acc[0]);
            acc[1] = ffma2(a, bv.y, acc[1]);
        }
    }
}

__device__ __forceinline__ void st_acc(float* dst, u64t acc0, u64t acc1) {
    ulonglong2 v; v.x = acc0; v.y = acc1;
    *reinterpret_cast<ulonglong2*>(dst) = v;
}

// ---------------------------------------------------------------------------
// One CTA per batch image. Sinkhorn in the multiplicative (scaling) domain:
//   a = e^{u/eps}, b = e^{v/eps};  a <- mu*a/(a*(K b K) + 1e-6), etc.
// Algebraically identical to the reference log-domain update (+1e-6 lse).
// ---------------------------------------------------------------------------
__global__ __launch_bounds__(NTHREADS)
void sinkhorn_kernel(const float* __restrict__ y, const float* __restrict__ yt,
                     float* __restrict__ out, int nb) {
    __shared__ __align__(16) float sK[NSIDE * LDW];
    __shared__ __align__(16) float sA[NSIDE * LDW];
    __shared__ __align__(16) float sB[NSIDE * LDW];
    __shared__ __align__(16) float sT[NSIDE * LDW];
    __shared__ float ktab[NSIDE];
    __shared__ float kdtab[NSIDE];
    __shared__ float red[NWARPS];

    const int tid  = threadIdx.x;
    const int wid  = tid >> 5;
    const int lane = tid & 31;
    const int wrb  = wid / 3;            // warp row-block 0..5
    const int wc   = wid % 3;            // warp col-block 0..2
    const int lr   = lane >> 2;          // row slot 0..7
    const int lc   = lane & 3;           // col slot 0..3
    const int rA   = wrb * 8 + lr;       // this thread's row
    const int c0   = wc * 16 + lc * 4;   // col block (4 cols)

    const float* yb  = y  + (size_t)blockIdx.x * NPIX;
    const float* ytb = yt + (size_t)blockIdx.x * NPIX;

    if (tid < NSIDE) {
        float dd = (float)tid * (1.0f / 48.0f);
        float d2 = dd * dd;
        float k  = expf(-d2 * INV_EPS);
        ktab[tid]  = k;
        kdtab[tid] = k * d2;
    }
    for (int i = tid; i < NPIX; i += NTHREADS) {
        int ro = i / NSIDE, co = i % NSIDE;
        int d  = ro - co; d = d < 0 ? -d : d;
        float dd = (float)d * (1.0f / 48.0f);
        sK[ro * LDW + co] = expf(-dd * dd * INV_EPS);
    }

    float sxl = 0.0f, syl = 0.0f;
    for (int i = tid; i < NPIX; i += NTHREADS) {
        sxl += mass_of(yb[i]);
        syl += mass_of(ytb[i]);
    }
    __syncthreads();
    const float sx = block_reduce(sxl, red);
    const float sy = block_reduce(syl, red);
    const float rsx = 1.0f / sx, rsy = 1.0f / sy;

    // per-thread mu/nu (1 row x 4 cols), init a=b=1
    float4 mu4, nu4, a4, b4;
    {
        int gidx = rA * NSIDE + c0;
        float4 yv  = ld4(yb  + gidx);
        float4 ytv = ld4(ytb + gidx);
        mu4 = make_float4(mass_of(yv.x) * rsx, mass_of(yv.y) * rsx,
                          mass_of(yv.z) * rsx, mass_of(yv.w) * rsx);
        nu4 = make_float4(mass_of(ytv.x) * rsy, mass_of(ytv.y) * rsy,
                          mass_of(ytv.z) * rsy, mass_of(ytv.w) * rsy);
        a4 = make_float4(1.f, 1.f, 1.f, 1.f);
        b4 = make_float4(1.f, 1.f, 1.f, 1.f);
        st4(&sA[rA * LDW + c0], a4);
        st4(&sB[rA * LDW + c0], b4);
    }
    __syncthreads();

    u64t t[2], s[2];
#pragma unroll 1
    for (int it = 0; it < 5; it++) {
        // u-update: S = K*B*K ; a <- mu*a / (a*S + 1e-6)
        mm_wb(sK, sB, rA, c0, t);
        st_acc(&sT[rA * LDW + c0], t[0], t[1]);
        __syncthreads();
        mm_wb(sT, sK, rA, c0, s);
        {
            float2 slo = unpack2(s[0]);
            float2 shi = unpack2(s[1]);
            a4.x = __fdividef(mu4.x * a4.x, fmaf(a4.x, slo.x, 1e-6f));
            a4.y = __fdividef(mu4.y * a4.y, fmaf(a4.y, slo.y, 1e-6f));
            a4.z = __fdividef(mu4.z * a4.z, fmaf(a4.z, shi.x, 1e-6f));
            a4.w = __fdividef(mu4.w * a4.w, fmaf(a4.w, shi.y, 1e-6f));
            st4(&sA[rA * LDW + c0], a4);
        }
        __syncthreads();

        // v-update: S = K*A*K ; b <- nu*b / (b*S + 1e-6)
        mm_wb(sK, sA, rA, c0, t);
        st_acc(&sT[rA * LDW + c0], t[0], t[1]);
        __syncthreads();
        mm_wb(sT, sK, rA, c0, s);
        {
            float2 slo = unpack2(s[0]);
            float2 shi = unpack2(s[1]);
            b4.x = __fdividef(nu4.x * b4.x, fmaf(b4.x, slo.x, 1e-6f));
            b4.y = __fdividef(nu4.y * b4.y, fmaf(b4.y, slo.y, 1e-6f));
            b4.z = __fdividef(nu4.z * b4.z, fmaf(b4.z, shi.x, 1e-6f));
            b4.w = __fdividef(nu4.w * b4.w, fmaf(b4.w, shi.y, 1e-6f));
            st4(&sB[rA * LDW + c0], b4);
        }
        __syncthreads();
    }

    // cost = sum_i a_i * [ (KD*B*K) + (K*B*KD) ]_i  — 2 fused passes.
    // Pass 1: T1 = KD*B (-> sT), T2 = K*B (-> sA; a lives in registers).
    {
        float4 t1 = make_float4(0.f, 0.f, 0.f, 0.f);
        float4 t2 = make_float4(0.f, 0.f, 0.f, 0.f);
#pragma unroll 8
        for (int b = 0; b < NSIDE; b++) {
            int d0 = rA - b; d0 = d0 < 0 ? -d0 : d0;
            float kd0 = kdtab[d0];
            float k0  = ktab[d0];
            float4 bv = ld4(sB + b * LDW + c0);
            t1.x = fmaf(kd0, bv.x, t1.x); t1.y = fmaf(kd0, bv.y, t1.y);
            t1.z = fmaf(kd0, bv.z, t1.z); t1.w = fmaf(kd0, bv.w, t1.w);
            t2.x = fmaf(k0, bv.x, t2.x);  t2.y = fmaf(k0, bv.y, t2.y);
            t2.z = fmaf(k0, bv.z, t2.z);  t2.w = fmaf(k0, bv.w, t2.w);
        }
        st4(&sT[rA * LDW + c0], t1);
        st4(&sA[rA * LDW + c0], t2);
        __syncthreads();
    }

    // Pass 2: S1 = T1*K, S2 = T2*KD; cl = sum a .* (S1 + S2)
    float cl = 0.0f;
    {
        float4 s1 = make_float4(0.f, 0.f, 0.f, 0.f);
        float4 s2 = make_float4(0.f, 0.f, 0.f, 0.f);
        const float* t1p = sT + rA * LDW;
        const float* t2p = sA + rA * LDW;
#pragma unroll 8
        for (int b = 0; b < NSIDE; b++) {
            float p0 = t1p[b];
            float q0 = t2p[b];
            float4 kv = ld4(sK + b * LDW + c0);
            int e0 = b - c0;     e0 = e0 < 0 ? -e0 : e0;
            int e1 = b - c0 - 1; e1 = e1 < 0 ? -e1 : e1;
            int e2 = b - c0 - 2; e2 = e2 < 0 ? -e2 : e2;
            int e3 = b - c0 - 3; e3 = e3 < 0 ? -e3 : e3;
            float kd0 = kdtab[e0], kd1 = kdtab[e1], kd2 = kdtab[e2], kd3 = kdtab[e3];
            s1.x = fmaf(p0, kv.x, s1.x); s1.y = fmaf(p0, kv.y, s1.y);
            s1.z = fmaf(p0, kv.z, s1.z); s1.w = fmaf(p0, kv.w, s1.w);
            s2.x = fmaf(q0, kd0, s2.x);  s2.y = fmaf(q0, kd1, s2.y);
            s2.z = fmaf(q0, kd2, s2.z);  s2.w = fmaf(q0, kd3, s2.w);
        }
        cl += a4.x * (s1.x + s2.x);
        cl += a4.y * (s1.y + s2.y);
        cl += a4.z * (s1.z + s2.z);
        cl += a4.w * (s1.w + s2.w);
    }

    float c = block_reduce(cl, red);

    // last CTA finalizes the batch mean (counter self-resets: replay-safe)
    if (tid == 0) {
        g_cost[blockIdx.x] = c;
        __threadfence();
        unsigned done = atomicAdd(&g_count, 1u);
        if (done == (unsigned)(nb - 1)) {
            float ssum = 0.0f;
            for (int i = 0; i < nb; i++) ssum += g_cost[i];
            *out = ssum / (float)nb;
            g_count = 0;
        }
    }
}

extern "C" void kernel_launch(void* const* d_in, const int* in_sizes, int n_in,
                              void* d_out, int out_size) {
    const float* y  = (const float*)d_in[0];
    const float* yt = (const float*)d_in[1];
    float* out = (float*)d_out;

    int nb = in_sizes[0] / NPIX;   // 16
    if (nb < 1)    nb = 1;
    if (nb > MAXB) nb = MAXB;

    sinkhorn_kernel<<<nb, NTHREADS>>>(y, yt, out, nb);
}

// round 14
// speedup vs baseline: 1.5879x; 1.5879x over previous
#include <cuda_runtime.h>

#define NSIDE    48
#define NPIX     2304          // 48*48
#define LDW      52            // padded smem row stride (floats)
#define NTHREADS 288           // 9 warps: 3x3 grid of 16x16 warp tiles
#define NWARPS   9
#define INV_EPS  100.0f
#define MAXB     64

__device__ float g_cost[MAXB];
__device__ unsigned int g_count = 0;

typedef unsigned long long u64t;

__device__ __forceinline__ float4 ld4(const float* p) {
    return *reinterpret_cast<const float4*>(p);
}
__device__ __forceinline__ void st4(float* p, float4 v) {
    *reinterpret_cast<float4*>(p) = v;
}
__device__ __forceinline__ float mass_of(float x) {
    return fminf(fmaxf(x, 0.0f), 1e9f) + 1e-9f;
}

// ---- packed f32x2 helpers --------------------------------------------------
__device__ __forceinline__ u64t pack2(float v) {
    u64t r; asm("mov.b64 %0, {%1, %1};" : "=l"(r) : "f"(v)); return r;
}
__device__ __forceinline__ u64t ffma2(u64t a, u64t b, u64t c) {
    u64t d; asm("fma.rn.f32x2 %0, %1, %2, %3;" : "=l"(d) : "l"(a), "l"(b), "l"(c));
    return d;
}
__device__ __forceinline__ float2 unpack2(u64t v) {
    float2 f; asm("mov.b64 {%0, %1}, %2;" : "=f"(f.x), "=f"(f.y) : "l"(v));
    return f;
}

// ---------------------------------------------------------------------------
// block reduce (all threads receive the sum; deterministic order)
// ---------------------------------------------------------------------------
__device__ __forceinline__ float block_reduce(float val, float* red) {
#pragma unroll
    for (int o = 16; o; o >>= 1) val += __shfl_down_sync(0xffffffffu, val, o);
    if ((threadIdx.x & 31) == 0) red[threadIdx.x >> 5] = val;
    __syncthreads();
    float s = red[0];
#pragma unroll
    for (int w = 1; w < NWARPS; w++) s += red[w];
    __syncthreads();
    return s;
}

// ---------------------------------------------------------------------------
// Dense 48x48 matmul slice, 16x16 warp tiles, software-pipelined:
// loads for chunk c+1 (2x A LDS.128 + 4x B LDS.128) issue before the 16
// FFMA2 of chunk c, hiding the 29-cyc LDS latency within one warp.
// ---------------------------------------------------------------------------
__device__ __forceinline__ void mm_wb(const float* __restrict__ A,
                                      const float* __restrict__ B,
                                      int rA, int rB, int c0, u64t acc[2][2]) {
    acc[0][0] = acc[0][1] = acc[1][0] = acc[1][1] = 0ull;
    const float* a0p = A + rA * LDW;
    const float* a1p = A + rB * LDW;
    const float* bp  = B + c0;

    float4 av0 = ld4(a0p);
    float4 av1 = ld4(a1p);
    ulonglong2 b0 = *reinterpret_cast<const ulonglong2*>(bp);
    ulonglong2 b1 = *reinterpret_cast<const ulonglong2*>(bp + LDW);
    ulonglong2 b2 = *reinterpret_cast<const ulonglong2*>(bp + 2 * LDW);
    ulonglong2 b3 = *reinterpret_cast<const ulonglong2*>(bp + 3 * LDW);

#pragma unroll
    for (int ch = 0; ch < 12; ch++) {
        float4 ca0 = av0, ca1 = av1;
        ulonglong2 cb0 = b0, cb1 = b1, cb2 = b2, cb3 = b3;
        if (ch < 11) {
            int nb = (ch + 1) * 4;
            av0 = ld4(a0p + nb);
            av1 = ld4(a1p + nb);
            const float* nbp = bp + nb * LDW;
            b0 = *reinterpret_cast<const ulonglong2*>(nbp);
            b1 = *reinterpret_cast<const ulonglong2*>(nbp + LDW);
            b2 = *reinterpret_cast<const ulonglong2*>(nbp + 2 * LDW);
            b3 = *reinterpret_cast<const ulonglong2*>(nbp + 3 * LDW);
        }
        u64t pa;
        pa = pack2(ca0.x); acc[0][0] = ffma2(pa, cb0.x, acc[0][0]); acc[0][1] = ffma2(pa, cb0.y, acc[0][1]);
        pa = pack2(ca1.x); acc[1][0] = ffma2(pa, cb0.x, acc[1][0]); acc[1][1] = ffma2(pa, cb0.y, acc[1][1]);
        pa = pack2(ca0.y); acc[0][0] = ffma2(pa, cb1.x, acc[0][0]); acc[0][1] = ffma2(pa, cb1.y, acc[0][1]);
        pa = pack2(ca1.y); acc[1][0] = ffma2(pa, cb1.x, acc[1][0]); acc[1][1] = ffma2(pa, cb1.y, acc[1][1]);
        pa = pack2(ca0.z); acc[0][0] = ffma2(pa, cb2.x, acc[0][0]); acc[0][1] = ffma2(pa, cb2.y, acc[0][1]);
        pa = pack2(ca1.z); acc[1][0] = ffma2(pa, cb2.x, acc[1][0]); acc[1][1] = ffma2(pa, cb2.y, acc[1][1]);
        pa = pack2(ca0.w); acc[0][0] = ffma2(pa, cb3.x, acc[0][0]); acc[0][1] = ffma2(pa, cb3.y, acc[0][1]);
        pa = pack2(ca1.w); acc[1][0] = ffma2(pa, cb3.x, acc[1][0]); acc[1][1] = ffma2(pa, cb3.y, acc[1][1]);
    }
}

__device__ __forceinline__ void st_acc(float* dst, u64t acc0, u64t acc1) {
    ulonglong2 v; v.x = acc0; v.y = acc1;
    *reinterpret_cast<ulonglong2*>(dst) = v;
}

// ---------------------------------------------------------------------------
// One CTA per batch image. Sinkhorn in the multiplicative (scaling) domain:
//   a = e^{u/eps}, b = e^{v/eps};  a <- mu*a/(a*(K b K) + 1e-6), etc.
// Algebraically identical to the reference log-domain update (+1e-6 lse).
// ---------------------------------------------------------------------------
__global__ __launch_bounds__(NTHREADS)
void sinkhorn_kernel(const float* __restrict__ y, const float* __restrict__ yt,
                     float* __restrict__ out, int nb) {
    __shared__ __align__(16) float sK[NSIDE * LDW];
    __shared__ __align__(16) float sA[NSIDE * LDW];
    __shared__ __align__(16) float sB[NSIDE * LDW];
    __shared__ __align__(16) float sT[NSIDE * LDW];
    __shared__ float ktab[NSIDE];
    __shared__ float kdtab[NSIDE];
    __shared__ float red[NWARPS];

    const int tid  = threadIdx.x;
    const int wid  = tid >> 5;
    const int lane = tid & 31;
    const int wr   = wid / 3;            // warp row-block 0..2
    const int wc   = wid % 3;            // warp col-block 0..2
    const int lr   = lane >> 2;          // row slot 0..7
    const int lc   = lane & 3;           // col slot 0..3
    const int rA   = wr * 16 + lr;       // first row
    const int rB   = rA + 8;             // second row
    const int c0   = wc * 16 + lc * 4;   // col block

    const float* yb  = y  + (size_t)blockIdx.x * NPIX;
    const float* ytb = yt + (size_t)blockIdx.x * NPIX;

    if (tid < NSIDE) {
        float dd = (float)tid * (1.0f / 48.0f);
        float d2 = dd * dd;
        float k  = expf(-d2 * INV_EPS);
        ktab[tid]  = k;
        kdtab[tid] = k * d2;
    }
    for (int i = tid; i < NPIX; i += NTHREADS) {
        int ro = i / NSIDE, co = i % NSIDE;
        int d  = ro - co; d = d < 0 ? -d : d;
        float dd = (float)d * (1.0f / 48.0f);
        sK[ro * LDW + co] = expf(-dd * dd * INV_EPS);
    }

    float sxl = 0.0f, syl = 0.0f;
    for (int i = tid; i < NPIX; i += NTHREADS) {
        sxl += mass_of(yb[i]);
        syl += mass_of(ytb[i]);
    }
    __syncthreads();
    const float sx = block_reduce(sxl, red);
    const float sy = block_reduce(syl, red);
    const float rsx = 1.0f / sx, rsy = 1.0f / sy;

    float4 mu4[2], nu4[2], a4[2], b4[2];
    const int rows[2] = {rA, rB};
#pragma unroll
    for (int i = 0; i < 2; i++) {
        int gidx = rows[i] * NSIDE + c0;
        float4 yv  = ld4(yb  + gidx);
        float4 ytv = ld4(ytb + gidx);
        mu4[i] = make_float4(mass_of(yv.x) * rsx, mass_of(yv.y) * rsx,
                             mass_of(yv.z) * rsx, mass_of(yv.w) * rsx);
        nu4[i] = make_float4(mass_of(ytv.x) * rsy, mass_of(ytv.y) * rsy,
                             mass_of(ytv.z) * rsy, mass_of(ytv.w) * rsy);
        a4[i] = make_float4(1.f, 1.f, 1.f, 1.f);
        b4[i] = make_float4(1.f, 1.f, 1.f, 1.f);
        st4(&sA[rows[i] * LDW + c0], a4[i]);
        st4(&sB[rows[i] * LDW + c0], b4[i]);
    }
    __syncthreads();

    // 5 Sinkhorn iterations; u-update (h=0) and v-update (h=1) share one body
    // to keep the (fully unrolled) matmul code inside the 32KB I$.
    u64t t[2][2], s[2][2];
#pragma unroll 1
    for (int it = 0; it < 5; it++) {
#pragma unroll 1
        for (int h = 0; h < 2; h++) {
            const float* X = h ? sA : sB;            // X operand
            float* D       = h ? sB : sA;            // destination scalings
            mm_wb(sK, X, rA, rB, c0, t);
            st_acc(&sT[rA * LDW + c0], t[0][0], t[0][1]);
            st_acc(&sT[rB * LDW + c0], t[1][0], t[1][1]);
            __syncthreads();
            mm_wb(sT, sK, rA, rB, c0, s);
#pragma unroll
            for (int i = 0; i < 2; i++) {
                float4 mv = h ? nu4[i] : mu4[i];
                float4 xv = h ? b4[i]  : a4[i];
                float2 slo = unpack2(s[i][0]);
                float2 shi = unpack2(s[i][1]);
                float4 nx;
                nx.x = __fdividef(mv.x * xv.x, fmaf(xv.x, slo.x, 1e-6f));
                nx.y = __fdividef(mv.y * xv.y, fmaf(xv.y, slo.y, 1e-6f));
                nx.z = __fdividef(mv.z * xv.z, fmaf(xv.z, shi.x, 1e-6f));
                nx.w = __fdividef(mv.w * xv.w, fmaf(xv.w, shi.y, 1e-6f));
                if (h) b4[i] = nx; else a4[i] = nx;
                st4(&D[rows[i] * LDW + c0], nx);
            }
            __syncthreads();
        }
    }

    // cost = sum_i a_i * [ (KD*B*K) + (K*B*KD) ]_i  — 2 fused passes.
    // Pass 1: T1 = KD*B (-> sT), T2 = K*B (-> sA; a lives in registers).
    {
        float4 t1[2], t2[2];
        t1[0] = t1[1] = t2[0] = t2[1] = make_float4(0.f, 0.f, 0.f, 0.f);
#pragma unroll 8
        for (int b = 0; b < NSIDE; b++) {
            int d0 = rA - b; d0 = d0 < 0 ? -d0 : d0;
            int d1 = rB - b; d1 = d1 < 0 ? -d1 : d1;
            float kd0 = kdtab[d0], kd1 = kdtab[d1];
            float k0  = ktab[d0],  k1  = ktab[d1];
            float4 bv = ld4(sB + b * LDW + c0);
            t1[0].x = fmaf(kd0, bv.x, t1[0].x); t1[0].y = fmaf(kd0, bv.y, t1[0].y);
            t1[0].z = fmaf(kd0, bv.z, t1[0].z); t1[0].w = fmaf(kd0, bv.w, t1[0].w);
            t1[1].x = fmaf(kd1, bv.x, t1[1].x); t1[1].y = fmaf(kd1, bv.y, t1[1].y);
            t1[1].z = fmaf(kd1, bv.z, t1[1].z); t1[1].w = fmaf(kd1, bv.w, t1[1].w);
            t2[0].x = fmaf(k0, bv.x, t2[0].x);  t2[0].y = fmaf(k0, bv.y, t2[0].y);
            t2[0].z = fmaf(k0, bv.z, t2[0].z);  t2[0].w = fmaf(k0, bv.w, t2[0].w);
            t2[1].x = fmaf(k1, bv.x, t2[1].x);  t2[1].y = fmaf(k1, bv.y, t2[1].y);
            t2[1].z = fmaf(k1, bv.z, t2[1].z);  t2[1].w = fmaf(k1, bv.w, t2[1].w);
        }
        __syncthreads();
        st4(&sT[rA * LDW + c0], t1[0]);
        st4(&sT[rB * LDW + c0], t1[1]);
        st4(&sA[rA * LDW + c0], t2[0]);
        st4(&sA[rB * LDW + c0], t2[1]);
        __syncthreads();
    }

    // Pass 2: S1 = T1*K, S2 = T2*KD; cl = sum a .* (S1 + S2)
    float cl = 0.0f;
    {
        float4 s1[2], s2[2];
        s1[0] = s1[1] = s2[0] = s2[1] = make_float4(0.f, 0.f, 0.f, 0.f);
        const float* t1p0 = sT + rA * LDW;
        const float* t1p1 = sT + rB * LDW;
        const float* t2p0 = sA + rA * LDW;
        const float* t2p1 = sA + rB * LDW;
#pragma unroll 8
        for (int b = 0; b < NSIDE; b++) {
            float p0 = t1p0[b], p1 = t1p1[b];
            float q0 = t2p0[b], q1 = t2p1[b];
            float4 kv = ld4(sK + b * LDW + c0);
            int e0 = b - c0;     e0 = e0 < 0 ? -e0 : e0;
            int e1 = b - c0 - 1; e1 = e1 < 0 ? -e1 : e1;
            int e2 = b - c0 - 2; e2 = e2 < 0 ? -e2 : e2;
            int e3 = b - c0 - 3; e3 = e3 < 0 ? -e3 : e3;
            float kd0 = kdtab[e0], kd1 = kdtab[e1], kd2 = kdtab[e2], kd3 = kdtab[e3];
            s1[0].x = fmaf(p0, kv.x, s1[0].x); s1[0].y = fmaf(p0, kv.y, s1[0].y);
            s1[0].z = fmaf(p0, kv.z, s1[0].z); s1[0].w = fmaf(p0, kv.w, s1[0].w);
            s1[1].x = fmaf(p1, kv.x, s1[1].x); s1[1].y = fmaf(p1, kv.y, s1[1].y);
            s1[1].z = fmaf(p1, kv.z, s1[1].z); s1[1].w = fmaf(p1, kv.w, s1[1].w);
            s2[0].x = fmaf(q0, kd0, s2[0].x);  s2[0].y = fmaf(q0, kd1, s2[0].y);
            s2[0].z = fmaf(q0, kd2, s2[0].z);  s2[0].w = fmaf(q0, kd3, s2[0].w);
            s2[1].x = fmaf(q1, kd0, s2[1].x);  s2[1].y = fmaf(q1, kd1, s2[1].y);
            s2[1].z = fmaf(q1, kd2, s2[1].z);  s2[1].w = fmaf(q1, kd3, s2[1].w);
        }
#pragma unroll
        for (int i = 0; i < 2; i++) {
            cl += a4[i].x * (s1[i].x + s2[i].x);
            cl += a4[i].y * (s1[i].y + s2[i].y);
            cl += a4[i].z * (s1[i].z + s2[i].z);
            cl += a4[i].w * (s1[i].w + s2[i].w);
        }
    }

    float c = block_reduce(cl, red);

    // last CTA finalizes the batch mean (counter self-resets: replay-safe)
    if (tid == 0) {
        g_cost[blockIdx.x] = c;
        __threadfence();
        unsigned done = atomicAdd(&g_count, 1u);
        if (done == (unsigned)(nb - 1)) {
            float ssum = 0.0f;
            for (int i = 0; i < nb; i++) ssum += g_cost[i];
            *out = ssum / (float)nb;
            g_count = 0;
        }
    }
}

extern "C" void kernel_launch(void* const* d_in, const int* in_sizes, int n_in,
                              void* d_out, int out_size) {
    const float* y  = (const float*)d_in[0];
    const float* yt = (const float*)d_in[1];
    float* out = (float*)d_out;

    int nb = in_sizes[0] / NPIX;   // 16
    if (nb < 1)    nb = 1;
    if (nb > MAXB) nb = MAXB;

    sinkhorn_kernel<<<nb, NTHREADS>>>(y, yt, out, nb);
}

// round 15
// speedup vs baseline: 1.7878x; 1.1259x over previous
#include <cuda_runtime.h>

#define NSIDE    48
#define NPIX     2304          // 48*48
#define LDW      52            // padded smem row stride (floats)
#define NTHREADS 192           // 6 warps: 2x3 grid of 24x16 warp tiles
#define NWARPS   6
#define INV_EPS  100.0f
#define MAXB     64

__device__ float g_cost[MAXB];
__device__ unsigned int g_count = 0;

typedef unsigned long long u64t;

__device__ __forceinline__ float4 ld4(const float* p) {
    return *reinterpret_cast<const float4*>(p);
}
__device__ __forceinline__ void st4(float* p, float4 v) {
    *reinterpret_cast<float4*>(p) = v;
}
__device__ __forceinline__ float mass_of(float x) {
    return fminf(fmaxf(x, 0.0f), 1e9f) + 1e-9f;
}

// ---- packed f32x2 helpers --------------------------------------------------
__device__ __forceinline__ u64t pack2(float v) {
    u64t r; asm("mov.b64 %0, {%1, %1};" : "=l"(r) : "f"(v)); return r;
}
__device__ __forceinline__ u64t ffma2(u64t a, u64t b, u64t c) {
    u64t d; asm("fma.rn.f32x2 %0, %1, %2, %3;" : "=l"(d) : "l"(a), "l"(b), "l"(c));
    return d;
}
__device__ __forceinline__ float2 unpack2(u64t v) {
    float2 f; asm("mov.b64 {%0, %1}, %2;" : "=f"(f.x), "=f"(f.y) : "l"(v));
    return f;
}

// ---------------------------------------------------------------------------
// block reduce (all threads receive the sum; deterministic order)
// ---------------------------------------------------------------------------
__device__ __forceinline__ float block_reduce(float val, float* red) {
#pragma unroll
    for (int o = 16; o; o >>= 1) val += __shfl_down_sync(0xffffffffu, val, o);
    if ((threadIdx.x & 31) == 0) red[threadIdx.x >> 5] = val;
    __syncthreads();
    float s = red[0];
#pragma unroll
    for (int w = 1; w < NWARPS; w++) s += red[w];
    __syncthreads();
    return s;
}

// ---------------------------------------------------------------------------
// Dense 48x48 matmul slice, 24x16 warp tiles, 3 rows x 4 cols per thread,
// software-pipelined: loads for chunk c+1 (3x A LDS.128 + 4x B LDS.128)
// issue before the 24 FFMA2 of chunk c.
// ---------------------------------------------------------------------------
__device__ __forceinline__ void mm_wb(const float* __restrict__ A,
                                      const float* __restrict__ B,
                                      int r0, int c0, u64t acc[3][2]) {
#pragma unroll
    for (int i = 0; i < 3; i++) { acc[i][0] = 0ull; acc[i][1] = 0ull; }
    const float* a0p = A + r0 * LDW;
    const float* a1p = a0p + LDW;
    const float* a2p = a1p + LDW;
    const float* bp  = B + c0;

    float4 av0 = ld4(a0p);
    float4 av1 = ld4(a1p);
    float4 av2 = ld4(a2p);
    ulonglong2 b0 = *reinterpret_cast<const ulonglong2*>(bp);
    ulonglong2 b1 = *reinterpret_cast<const ulonglong2*>(bp + LDW);
    ulonglong2 b2 = *reinterpret_cast<const ulonglong2*>(bp + 2 * LDW);
    ulonglong2 b3 = *reinterpret_cast<const ulonglong2*>(bp + 3 * LDW);

#pragma unroll
    for (int ch = 0; ch < 12; ch++) {
        float4 ca0 = av0, ca1 = av1, ca2 = av2;
        ulonglong2 cb0 = b0, cb1 = b1, cb2 = b2, cb3 = b3;
        if (ch < 11) {
            int nb = (ch + 1) * 4;
            av0 = ld4(a0p + nb);
            av1 = ld4(a1p + nb);
            av2 = ld4(a2p + nb);
            const float* nbp = bp + nb * LDW;
            b0 = *reinterpret_cast<const ulonglong2*>(nbp);
            b1 = *reinterpret_cast<const ulonglong2*>(nbp + LDW);
            b2 = *reinterpret_cast<const ulonglong2*>(nbp + 2 * LDW);
            b3 = *reinterpret_cast<const ulonglong2*>(nbp + 3 * LDW);
        }
        u64t pa;
        pa = pack2(ca0.x); acc[0][0] = ffma2(pa, cb0.x, acc[0][0]); acc[0][1] = ffma2(pa, cb0.y, acc[0][1]);
        pa = pack2(ca1.x); acc[1][0] = ffma2(pa, cb0.x, acc[1][0]); acc[1][1] = ffma2(pa, cb0.y, acc[1][1]);
        pa = pack2(ca2.x); acc[2][0] = ffma2(pa, cb0.x, acc[2][0]); acc[2][1] = ffma2(pa, cb0.y, acc[2][1]);
        pa = pack2(ca0.y); acc[0][0] = ffma2(pa, cb1.x, acc[0][0]); acc[0][1] = ffma2(pa, cb1.y, acc[0][1]);
        pa = pack2(ca1.y); acc[1][0] = ffma2(pa, cb1.x, acc[1][0]); acc[1][1] = ffma2(pa, cb1.y, acc[1][1]);
        pa = pack2(ca2.y); acc[2][0] = ffma2(pa, cb1.x, acc[2][0]); acc[2][1] = ffma2(pa, cb1.y, acc[2][1]);
        pa = pack2(ca0.z); acc[0][0] = ffma2(pa, cb2.x, acc[0][0]); acc[0][1] = ffma2(pa, cb2.y, acc[0][1]);
        pa = pack2(ca1.z); acc[1][0] = ffma2(pa, cb2.x, acc[1][0]); acc[1][1] = ffma2(pa, cb2.y, acc[1][1]);
        pa = pack2(ca2.z); acc[2][0] = ffma2(pa, cb2.x, acc[2][0]); acc[2][1] = ffma2(pa, cb2.y, acc[2][1]);
        pa = pack2(ca0.w); acc[0][0] = ffma2(pa, cb3.x, acc[0][0]); acc[0][1] = ffma2(pa, cb3.y, acc[0][1]);
        pa = pack2(ca1.w); acc[1][0] = ffma2(pa, cb3.x, acc[1][0]); acc[1][1] = ffma2(pa, cb3.y, acc[1][1]);
        pa = pack2(ca2.w); acc[2][0] = ffma2(pa, cb3.x, acc[2][0]); acc[2][1] = ffma2(pa, cb3.y, acc[2][1]);
    }
}

__device__ __forceinline__ void st_acc(float* dst, u64t acc0, u64t acc1) {
    ulonglong2 v; v.x = acc0; v.y = acc1;
    *reinterpret_cast<ulonglong2*>(dst) = v;
}

// ---------------------------------------------------------------------------
// One CTA per batch image. Sinkhorn in the multiplicative (scaling) domain:
//   a = e^{u/eps}, b = e^{v/eps};  a <- mu*a/(a*(K b K) + 1e-6), etc.
// Algebraically identical to the reference log-domain update (+1e-6 lse).
// ---------------------------------------------------------------------------
__global__ __launch_bounds__(NTHREADS)
void sinkhorn_kernel(const float* __restrict__ y, const float* __restrict__ yt,
                     float* __restrict__ out, int nb) {
    __shared__ __align__(16) float sK[NSIDE * LDW];
    __shared__ __align__(16) float sA[NSIDE * LDW];
    __shared__ __align__(16) float sB[NSIDE * LDW];
    __shared__ __align__(16) float sT[NSIDE * LDW];
    __shared__ float ktab[NSIDE];
    __shared__ float kdtab[NSIDE];
    __shared__ float red[NWARPS];

    const int tid  = threadIdx.x;
    const int wid  = tid >> 5;
    const int lane = tid & 31;
    const int wr   = wid / 3;            // warp row-block 0..1
    const int wc   = wid % 3;            // warp col-block 0..2
    const int lr   = lane >> 2;          // row slot 0..7
    const int lc   = lane & 3;           // col slot 0..3
    const int r0   = wr * 24 + lr * 3;   // rows r0, r0+1, r0+2
    const int c0   = wc * 16 + lc * 4;   // col block

    const float* yb  = y  + (size_t)blockIdx.x * NPIX;
    const float* ytb = yt + (size_t)blockIdx.x * NPIX;

    if (tid < NSIDE) {
        float dd = (float)tid * (1.0f / 48.0f);
        float d2 = dd * dd;
        float k  = expf(-d2 * INV_EPS);
        ktab[tid]  = k;
        kdtab[tid] = k * d2;
    }
    for (int i = tid; i < NPIX; i += NTHREADS) {
        int ro = i / NSIDE, co = i % NSIDE;
        int d  = ro - co; d = d < 0 ? -d : d;
        float dd = (float)d * (1.0f / 48.0f);
        sK[ro * LDW + co] = expf(-dd * dd * INV_EPS);
    }

    float sxl = 0.0f, syl = 0.0f;
    for (int i = tid; i < NPIX; i += NTHREADS) {
        sxl += mass_of(yb[i]);
        syl += mass_of(ytb[i]);
    }
    __syncthreads();
    const float sx = block_reduce(sxl, red);
    const float sy = block_reduce(syl, red);
    const float rsx = 1.0f / sx, rsy = 1.0f / sy;

    float4 mu4[3], nu4[3], a4[3], b4[3];
#pragma unroll
    for (int i = 0; i < 3; i++) {
        int gidx = (r0 + i) * NSIDE + c0;
        float4 yv  = ld4(yb  + gidx);
        float4 ytv = ld4(ytb + gidx);
        mu4[i] = make_float4(mass_of(yv.x) * rsx, mass_of(yv.y) * rsx,
                             mass_of(yv.z) * rsx, mass_of(yv.w) * rsx);
        nu4[i] = make_float4(mass_of(ytv.x) * rsy, mass_of(ytv.y) * rsy,
                             mass_of(ytv.z) * rsy, mass_of(ytv.w) * rsy);
        a4[i] = make_float4(1.f, 1.f, 1.f, 1.f);
        b4[i] = make_float4(1.f, 1.f, 1.f, 1.f);
        st4(&sA[(r0 + i) * LDW + c0], a4[i]);
        st4(&sB[(r0 + i) * LDW + c0], b4[i]);
    }
    __syncthreads();

    // 5 Sinkhorn iterations; u-update (h=0) and v-update (h=1) share one body
    // to keep the (fully unrolled) matmul code inside the I$.
    u64t t[3][2], s[3][2];
#pragma unroll 1
    for (int it = 0; it < 5; it++) {
#pragma unroll 1
        for (int h = 0; h < 2; h++) {
            const float* X = h ? sA : sB;            // X operand
            float* D       = h ? sB : sA;            // destination scalings
            mm_wb(sK, X, r0, c0, t);
#pragma unroll
            for (int i = 0; i < 3; i++)
                st_acc(&sT[(r0 + i) * LDW + c0], t[i][0], t[i][1]);
            __syncthreads();
            mm_wb(sT, sK, r0, c0, s);
#pragma unroll
            for (int i = 0; i < 3; i++) {
                float4 mv = h ? nu4[i] : mu4[i];
                float4 xv = h ? b4[i]  : a4[i];
                float2 slo = unpack2(s[i][0]);
                float2 shi = unpack2(s[i][1]);
                float4 nx;
                nx.x = __fdividef(mv.x * xv.x, fmaf(xv.x, slo.x, 1e-6f));
                nx.y = __fdividef(mv.y * xv.y, fmaf(xv.y, slo.y, 1e-6f));
                nx.z = __fdividef(mv.z * xv.z, fmaf(xv.z, shi.x, 1e-6f));
                nx.w = __fdividef(mv.w * xv.w, fmaf(xv.w, shi.y, 1e-6f));
                if (h) b4[i] = nx; else a4[i] = nx;
                st4(&D[(r0 + i) * LDW + c0], nx);
            }
            __syncthreads();
        }
    }

    // cost = sum_i a_i * [ (KD*B*K) + (K*B*KD) ]_i  — 2 fused passes.
    // Pass 1: T1 = KD*B (-> sT), T2 = K*B (-> sA; a lives in registers).
    {
        float4 t1[3], t2[3];
#pragma unroll
        for (int i = 0; i < 3; i++) {
            t1[i] = make_float4(0.f, 0.f, 0.f, 0.f);
            t2[i] = make_float4(0.f, 0.f, 0.f, 0.f);
        }
#pragma unroll 8
        for (int b = 0; b < NSIDE; b++) {
            float4 bv = ld4(sB + b * LDW + c0);
#pragma unroll
            for (int i = 0; i < 3; i++) {
                int d0 = r0 + i - b; d0 = d0 < 0 ? -d0 : d0;
                float kd = kdtab[d0];
                float kk = ktab[d0];
                t1[i].x = fmaf(kd, bv.x, t1[i].x); t1[i].y = fmaf(kd, bv.y, t1[i].y);
                t1[i].z = fmaf(kd, bv.z, t1[i].z); t1[i].w = fmaf(kd, bv.w, t1[i].w);
                t2[i].x = fmaf(kk, bv.x, t2[i].x); t2[i].y = fmaf(kk, bv.y, t2[i].y);
                t2[i].z = fmaf(kk, bv.z, t2[i].z); t2[i].w = fmaf(kk, bv.w, t2[i].w);
            }
        }
        __syncthreads();
#pragma unroll
        for (int i = 0; i < 3; i++) {
            st4(&sT[(r0 + i) * LDW + c0], t1[i]);
            st4(&sA[(r0 + i) * LDW + c0], t2[i]);
        }
        __syncthreads();
    }

    // Pass 2: S1 = T1*K, S2 = T2*KD; cl = sum a .* (S1 + S2)
    float cl = 0.0f;
    {
        float4 s1[3], s2[3];
#pragma unroll
        for (int i = 0; i < 3; i++) {
            s1[i] = make_float4(0.f, 0.f, 0.f, 0.f);
            s2[i] = make_float4(0.f, 0.f, 0.f, 0.f);
        }
#pragma unroll 8
        for (int b = 0; b < NSIDE; b++) {
            float4 kv = ld4(sK + b * LDW + c0);
            int e0 = b - c0;     e0 = e0 < 0 ? -e0 : e0;
            int e1 = b - c0 - 1; e1 = e1 < 0 ? -e1 : e1;
            int e2 = b - c0 - 2; e2 = e2 < 0 ? -e2 : e2;
            int e3 = b - c0 - 3; e3 = e3 < 0 ? -e3 : e3;
            float kd0 = kdtab[e0], kd1 = kdtab[e1], kd2 = kdtab[e2], kd3 = kdtab[e3];
#pragma unroll
            for (int i = 0; i < 3; i++) {
                float p0 = sT[(r0 + i) * LDW + b];
                float q0 = sA[(r0 + i) * LDW + b];
                s1[i].x = fmaf(p0, kv.x, s1[i].x); s1[i].y = fmaf(p0, kv.y, s1[i].y);
                s1[i].z = fmaf(p0, kv.z, s1[i].z); s1[i].w = fmaf(p0, kv.w, s1[i].w);
                s2[i].x = fmaf(q0, kd0, s2[i].x);  s2[i].y = fmaf(q0, kd1, s2[i].y);
                s2[i].z = fmaf(q0, kd2, s2[i].z);  s2[i].w = fmaf(q0, kd3, s2[i].w);
            }
        }
#pragma unroll
        for (int i = 0; i < 3; i++) {
            cl += a4[i].x * (s1[i].x + s2[i].x);
            cl += a4[i].y * (s1[i].y + s2[i].y);
            cl += a4[i].z * (s1[i].z + s2[i].z);
            cl += a4[i].w * (s1[i].w + s2[i].w);
        }
    }

    float c = block_reduce(cl, red);

    // last CTA finalizes the batch mean (counter self-resets: replay-safe)
    if (tid == 0) {
        g_cost[blockIdx.x] = c;
        __threadfence();
        unsigned done = atomicAdd(&g_count, 1u);
        if (done == (unsigned)(nb - 1)) {
            float ssum = 0.0f;
            for (int i = 0; i < nb; i++) ssum += g_cost[i];
            *out = ssum / (float)nb;
            g_count = 0;
        }
    }
}

extern "C" void kernel_launch(void* const* d_in, const int* in_sizes, int n_in,
                              void* d_out, int out_size) {
    const float* y  = (const float*)d_in[0];
    const float* yt = (const float*)d_in[1];
    float* out = (float*)d_out;

    int nb = in_sizes[0] / NPIX;   // 16
    if (nb < 1)    nb = 1;
    if (nb > MAXB) nb = MAXB;

    sinkhorn_kernel<<<nb, NTHREADS>>>(y, yt, out, nb);
}